// round 6
// baseline (speedup 1.0000x reference)
#include <cuda_runtime.h>
#include <math.h>

#define cB 32
#define cS 145
#define cC 768
#define cD 8192
#define cSN 64
#define MPAD 160

__device__ float g_se1[cB*cC];
__device__ float g_a1[cB*cD];
__device__ float g_a2[cB*cD];
__device__ float g_u1[cD];
__device__ float g_u2[cD];
__device__ float g_q0[cB*cD];
__device__ float g_q1[cB*cD];
__device__ float g_q2[cD];
__device__ float g_A[3*cB*MPAD];
__device__ int   g_flag;
__device__ float g_x1[cB*MPAD*cC];   // tf32-rounded X1t, k-permuted within 8-groups
__device__ float g_x2[cB*MPAD*cC];   // exact X2t

__device__ __forceinline__ unsigned int f2tf32(float f) {
    unsigned int u;
    asm("cvt.rna.tf32.f32 %0, %1;" : "=r"(u) : "f"(f));
    return u;
}
__device__ __forceinline__ unsigned smem_u32(const void* p) {
    unsigned a;
    asm("{ .reg .u64 t; cvta.to.shared.u64 t, %1; cvt.u32.u64 %0, t; }"
        : "=r"(a) : "l"(p));
    return a;
}
__device__ __forceinline__ void cpa16(unsigned dst, const void* src) {
    asm volatile("cp.async.cg.shared.global [%0], [%1], 16;" :: "r"(dst), "l"(src));
}
#define CPA_COMMIT() asm volatile("cp.async.commit_group;" ::: "memory")
#define CPA_WAIT0()  asm volatile("cp.async.wait_group 0;" ::: "memory")

// ---------------- k_init ---------------------------------------------------
__global__ void k_init()
{
    int idx = blockIdx.x*blockDim.x + threadIdx.x;
    int nt  = gridDim.x*blockDim.x;
    for (int i = idx; i < cB*cD; i += nt) { g_a1[i] = 0.f; g_a2[i] = 0.f; }
    for (int i = idx; i < cD;    i += nt) { g_u1[i] = 0.f; g_u2[i] = 0.f; }
    for (int i = idx; i < 3*cB*MPAD; i += nt) g_A[i] = 0.f;
    if (idx == 0) g_flag = 0;
}

// ---------------- k_prep: X1 (tf32, permuted) and X2 (exact) ---------------
__global__ void k_prep(const float* __restrict__ img, const float* __restrict__ tok,
                       const int* __restrict__ s1, const int* __restrict__ s2)
{
    int b = blockIdx.x, s = blockIdx.y;
    size_t o = (size_t)(b*MPAD + s)*cC;
    for (int c = threadIdx.x; c < cC; c += blockDim.x) {
        float f1 = (float)s1[c], f2 = (float)s2[c];
        float v = 0.f;
        if (s < cS) v = img[((size_t)b*cS + s)*cC + c] + tok[cC + c];
        int cp = (c & ~7) | (((c & 3) << 1) | ((c & 7) >> 2));   // sp(k)
        g_x1[o + cp] = __uint_as_float(f2tf32(v*f1));
        g_x2[o + c]  = v*f2;
    }
}

// ---------------- k_se1 ----------------------------------------------------
__global__ void k_se1(const float* __restrict__ sensor, const float* __restrict__ Wsen,
                      const float* __restrict__ bsen, const int* __restrict__ h1,
                      const int* __restrict__ h2, const float* __restrict__ b_s2,
                      const int* __restrict__ s1, const int* __restrict__ s2)
{
    int b = blockIdx.x, tid = threadIdx.x;
    __shared__ float ss[cSN];
    if (tid < cSN) ss[tid] = sensor[b*cSN + tid];
    if (b == 0 && tid < cS && b_s2[tid] != 0.f) atomicOr(&g_flag, 1);
    __syncthreads();
    for (int c = tid; c < cC; c += blockDim.x) {
        float acc = bsen[c];
        const float* w = Wsen + c*cSN;
        #pragma unroll 16
        for (int n = 0; n < cSN; ++n) acc += ss[n]*w[n];
        g_se1[b*cC + c] = acc;
        float f1 = (float)s1[c], f2 = (float)s2[c];
        atomicAdd(&g_a1[b*cD + h1[c]], acc*f1);
        atomicAdd(&g_a2[b*cD + h2[c]], acc*f2);
        if (b == 0) { atomicAdd(&g_u1[h1[c]], f1); atomicAdd(&g_u2[h2[c]], f2); }
    }
}

// ---------------- k_conv (unchanged fast path) -----------------------------
__global__ __launch_bounds__(256) void k_conv(const int* __restrict__ h2,
                                              const int* __restrict__ s2)
{
    extern __shared__ float smc[];
    float*  a1x = smc;
    float2* pt  = (float2*)(smc + 16384);

    int b = blockIdx.x, tid = threadIdx.x;
    for (int j = tid; j < cD; j += 256) {
        float v = g_a1[b*cD + j]; a1x[j] = v; a1x[j + cD] = v;
    }
    for (int c = tid; c < cC; c += 256) {
        pt[c] = make_float2(__int_as_float(cD - h2[c]),
                            g_se1[b*cC + c]*(float)s2[c]);
    }
    __syncthreads();

    int d0 = blockIdx.y*1024 + tid;
    float q0 = 0.f, q1 = 0.f, q2 = 0.f, q3 = 0.f;
    #pragma unroll 4
    for (int c = 0; c < cC; ++c) {
        float2 p = pt[c];
        int base = d0 + __float_as_int(p.x);
        q0 += p.y*a1x[base];
        q1 += p.y*a1x[base + 256];
        q2 += p.y*a1x[base + 512];
        q3 += p.y*a1x[base + 768];
    }
    float* qo = g_q0 + b*cD + d0;
    qo[0] = q0; qo[256] = q1; qo[512] = q2; qo[768] = q3;
}

// ---------------- k_conv_bias ----------------------------------------------
__global__ void k_conv_bias(const int* __restrict__ h1, const int* __restrict__ h2,
                            const int* __restrict__ s1, const int* __restrict__ s2)
{
    extern __shared__ float smc[];
    float* a1x  = smc;
    float* a2x  = smc + 16384;
    float* u1x  = smc + 32768;
    int*   psh2 = (int*)(smc + 49152);
    int*   psh1 = (int*)(smc + 49920);
    float* ps1  = smc + 51456;
    float* ps2  = smc + 52224;

    if (g_flag == 0) return;
    int b = blockIdx.x, tid = threadIdx.x;
    for (int j = tid; j < cD; j += 1024) {
        float v  = g_a1[b*cD + j]; a1x[j] = v;  a1x[j + cD] = v;
        float v2 = g_a2[b*cD + j]; a2x[j] = v2; a2x[j + cD] = v2;
        float v3 = g_u1[j];        u1x[j] = v3; u1x[j + cD] = v3;
    }
    if (tid < cC) {
        psh2[tid] = cD - h2[tid];
        psh1[tid] = cD - h1[tid];
        ps1[tid]  = (float)s1[tid];
        ps2[tid]  = (float)s2[tid];
    }
    __syncthreads();

    int d0 = blockIdx.y*2048 + tid, d1 = d0 + 1024;
    float q1a = 0.f, q1b = 0.f, q2a = 0.f, q2b = 0.f;
    for (int c = 0; c < cC; ++c) {
        int s2v = psh2[c], s1v = psh1[c];
        float f1 = ps1[c], f2 = ps2[c];
        q1a += f2*a1x[d0 + s2v] + f1*a2x[d0 + s1v];
        q1b += f2*a1x[d1 + s2v] + f1*a2x[d1 + s1v];
        q2a += f2*u1x[d0 + s2v];
        q2b += f2*u1x[d1 + s2v];
    }
    g_q1[b*cD + d0] = q1a; g_q1[b*cD + d1] = q1b;
    if (b == 0) { g_q2[d0] = q2a; g_q2[d1] = q2b; }
}

// ---------------- k_quad_mma: tf32 pipelined, M=160 x N=128 ----------------
// 8 warps = 2(wm) x 4(wn), warp tile 80x32, K-chunk 32, 24 iters, 2-stage
// cp.async pipeline on A, double-buffered gathered B.
#define STR 40
#define SQ_OFF   0                         // 8192 floats
#define SH1_OFF  8192                      // 768 ints
#define SRED_OFF (SH1_OFF + 768)           // 160
#define SA_OFF   (SRED_OFF + 160)          // 2 x 160*40 (16B aligned: 9120*4)
#define SB_OFF   (SA_OFF + 2*160*STR)      // 2 x 128*40
#define SMEM_Q   (SB_OFF + 2*128*STR)      // 32160 floats = 128640 B

__global__ __launch_bounds__(256, 1) void k_quad_mma(const int* __restrict__ h1,
                                                     const int* __restrict__ h2)
{
    extern __shared__ float sm[];
    float* sQ   = sm + SQ_OFF;
    int*   sH1  = (int*)(sm + SH1_OFF);
    float* sRed = sm + SRED_OFF;

    int b = blockIdx.x, c2base = blockIdx.y*128;
    int tid = threadIdx.x, lane = tid & 31, warp = tid >> 5;
    int wm = warp & 1, wn = warp >> 1;        // 2 x 4
    int t4 = lane & 3, qr = lane >> 2;

    const float* qsrc = g_q0 + b*cD;
    for (int j = tid; j < cD; j += 256) sQ[j] = __uint_as_float(f2tf32(qsrc[j]));
    for (int j = tid; j < cC; j += 256) {
        int p = j & 7;
        sH1[j] = h1[(j & ~7) | (((p & 1) << 2) | (p >> 1))];   // invp
    }
    if (tid < MPAD) sRed[tid] = 0.f;
    int h2v = h2[c2base + (tid >> 1)];
    int gn = tid >> 1, gk = (tid & 1)*16;
    __syncthreads();

    unsigned sb = smem_u32(sm);
    const float* x1p = g_x1 + (size_t)b*MPAD*cC;

    // prologue: stage r=0 into buf 0
    {
        unsigned abase = sb + (SA_OFF)*4;
        #pragma unroll
        for (int i = 0; i < 5; ++i) {
            int e = tid + i*256;
            int row = e >> 3, kq = e & 7;
            cpa16(abase + (row*STR + kq*4)*4, x1p + (size_t)row*cC + kq*4);
        }
        CPA_COMMIT();
        const int* h1r = sH1 + gk;
        float* bdst = sm + SB_OFF + gn*STR + gk;
        #pragma unroll 8
        for (int kk = 0; kk < 16; ++kk)
            bdst[kk] = sQ[(h1r[kk] + h2v) & (cD - 1)];
        CPA_WAIT0();
        __syncthreads();
    }

    float acc[5][4][4];
    #pragma unroll
    for (int mi = 0; mi < 5; ++mi)
        #pragma unroll
        for (int ni = 0; ni < 4; ++ni)
            #pragma unroll
            for (int j = 0; j < 4; ++j) acc[mi][ni][j] = 0.f;

    for (int r = 0; r < 24; ++r) {
        int buf = r & 1;
        // stage r+1 into buf^1 (overlaps mma below)
        if (r < 23) {
            unsigned abase = sb + (SA_OFF + (buf ^ 1)*160*STR)*4;
            const float* x1s = x1p + (r + 1)*32;
            #pragma unroll
            for (int i = 0; i < 5; ++i) {
                int e = tid + i*256;
                int row = e >> 3, kq = e & 7;
                cpa16(abase + (row*STR + kq*4)*4, x1s + (size_t)row*cC + kq*4);
            }
            CPA_COMMIT();
            const int* h1r = sH1 + (r + 1)*32 + gk;
            float* bdst = sm + SB_OFF + (buf ^ 1)*128*STR + gn*STR + gk;
            #pragma unroll 8
            for (int kk = 0; kk < 16; ++kk)
                bdst[kk] = sQ[(h1r[kk] + h2v) & (cD - 1)];
        }

        const float* At = sm + SA_OFF + buf*160*STR;
        const float* Bt = sm + SB_OFF + buf*128*STR;
        #pragma unroll
        for (int kb = 0; kb < 32; kb += 8) {
            float2 bfr[4];
            #pragma unroll
            for (int ni = 0; ni < 4; ++ni) {
                int n0 = wn*32 + ni*8 + qr;
                bfr[ni] = *(const float2*)(Bt + n0*STR + kb + 2*t4);
            }
            #pragma unroll
            for (int mi = 0; mi < 5; ++mi) {
                int rr = wm*80 + mi*16 + qr;
                float2 aA = *(const float2*)(At + rr*STR + kb + 2*t4);
                float2 aB = *(const float2*)(At + (rr + 8)*STR + kb + 2*t4);
                unsigned a0 = __float_as_uint(aA.x), a1r = __float_as_uint(aB.x);
                unsigned a2 = __float_as_uint(aA.y), a3 = __float_as_uint(aB.y);
                #pragma unroll
                for (int ni = 0; ni < 4; ++ni) {
                    asm volatile(
                        "mma.sync.aligned.m16n8k8.row.col.f32.tf32.tf32.f32 "
                        "{%0,%1,%2,%3}, {%4,%5,%6,%7}, {%8,%9}, {%0,%1,%2,%3};"
                        : "+f"(acc[mi][ni][0]), "+f"(acc[mi][ni][1]),
                          "+f"(acc[mi][ni][2]), "+f"(acc[mi][ni][3])
                        : "r"(a0), "r"(a1r), "r"(a2), "r"(a3),
                          "r"(__float_as_uint(bfr[ni].x)), "r"(__float_as_uint(bfr[ni].y)));
                }
            }
        }
        CPA_WAIT0();
        __syncthreads();
    }

    // epilogue: fold with exact fp32 X2
    const float* x2p = g_x2 + (size_t)b*MPAD*cC;
    #pragma unroll
    for (int mi = 0; mi < 5; ++mi) {
        int r0 = wm*80 + mi*16 + qr;
        int r1 = r0 + 8;
        float s0 = 0.f, s1v = 0.f;
        #pragma unroll
        for (int ni = 0; ni < 4; ++ni) {
            int col = c2base + wn*32 + ni*8 + 2*t4;
            float2 xa = *(const float2*)(x2p + (size_t)r0*cC + col);
            float2 xb = *(const float2*)(x2p + (size_t)r1*cC + col);
            s0  += acc[mi][ni][0]*xa.x + acc[mi][ni][1]*xa.y;
            s1v += acc[mi][ni][2]*xb.x + acc[mi][ni][3]*xb.y;
        }
        atomicAdd(&sRed[r0], s0);
        atomicAdd(&sRed[r1], s1v);
    }
    __syncthreads();
    if (tid < MPAD) atomicAdd(&g_A[b*MPAD + tid], sRed[tid]);
}

// ---------------- scalar quad for bias terms (z=1,2) -----------------------
__global__ __launch_bounds__(256) void k_quad_bias(const float* __restrict__ img,
                                                   const int* __restrict__ h1,
                                                   const int* __restrict__ h2,
                                                   const float* __restrict__ tok,
                                                   const int* __restrict__ s1,
                                                   const int* __restrict__ s2)
{
    extern __shared__ float smem[];
    float* sQ  = smem;
    float* sX1 = smem + 8192;
    float* sX2 = smem + 13344;
    int*   sH1 = (int*)(smem + 23584);
    float* sS1 = smem + 24352;
    float* sS2 = smem + 25120;
    float* sTk = smem + 25888;

    if (g_flag == 0) return;
    int z = blockIdx.z + 1;
    int b = blockIdx.x, c2base = blockIdx.y*64;
    int tx = threadIdx.x, ty = threadIdx.y, tid = ty*16 + tx;

    const float* qsrc = (z == 1) ? (g_q1 + b*cD) : g_q2;
    for (int j = tid; j < cD; j += 256) sQ[j] = qsrc[j];
    for (int j = tid; j < cC; j += 256) {
        sH1[j] = h1[j];
        sS1[j] = (float)s1[j]; sS2[j] = (float)s2[j];
        sTk[j] = tok[cC + j];
    }
    __syncthreads();

    for (int e = tid; e < MPAD*64; e += 256) {
        int c2l = e & 63, s = e >> 6;
        int c2 = c2base + c2l;
        float v = 0.f;
        if (s < cS) v = (img[(b*cS + s)*cC + c2] + sTk[c2])*sS2[c2];
        sX2[s*64 + c2l] = v;
    }

    int h2r[4];
    #pragma unroll
    for (int n = 0; n < 4; ++n) h2r[n] = h2[c2base + tx + 16*n];

    float acc[10][4];
    #pragma unroll
    for (int m = 0; m < 10; ++m)
        #pragma unroll
        for (int n = 0; n < 4; ++n) acc[m][n] = 0.f;

    for (int k0 = 0; k0 < cC; k0 += 32) {
        __syncthreads();
        #pragma unroll
        for (int i = 0; i < 20; ++i) {
            int e = tid + i*256;
            int kt = e & 31, s = e >> 5;
            int c1 = k0 + kt;
            float v = 0.f;
            if (s < cS) v = (img[(b*cS + s)*cC + c1] + sTk[c1])*sS1[c1];
            sX1[kt*161 + s] = v;
        }
        __syncthreads();
        #pragma unroll 8
        for (int kt = 0; kt < 32; ++kt) {
            int h1v = sH1[k0 + kt];
            float x1r[10];
            #pragma unroll
            for (int m = 0; m < 10; ++m) x1r[m] = sX1[kt*161 + ty + 16*m];
            float qv[4];
            #pragma unroll
            for (int n = 0; n < 4; ++n) qv[n] = sQ[(h1v + h2r[n]) & (cD - 1)];
            #pragma unroll
            for (int m = 0; m < 10; ++m)
                #pragma unroll
                for (int n = 0; n < 4; ++n)
                    acc[m][n] += x1r[m]*qv[n];
        }
    }

    #pragma unroll
    for (int m = 0; m < 10; ++m) {
        int s = ty + 16*m;
        float al = 0.f;
        #pragma unroll
        for (int n = 0; n < 4; ++n) al += acc[m][n]*sX2[s*64 + tx + 16*n];
        atomicAdd(&g_A[(z*cB + b)*MPAD + s], al);
    }
}

// ---------------- k_final --------------------------------------------------
__global__ void k_final(const float* __restrict__ W_s2, const float* __restrict__ b_s2,
                        const float* __restrict__ W_out, const float* __restrict__ b_out,
                        float* __restrict__ out)
{
    int tid = threadIdx.x;
    int b = tid >> 5, lane = tid & 31;
    float bpv[5]; float ssum = 0.f;
    #pragma unroll
    for (int i = 0; i < 5; ++i) {
        int s = lane + 32*i;
        float bp = 0.f;
        if (s < cS) {
            float w = W_s2[s], be = b_s2[s];
            float ip = w*w*g_A[b*MPAD + s]
                     + w*be*g_A[(cB + b)*MPAD + s]
                     + be*be*g_A[(2*cB + b)*MPAD + s];
            float sg = (ip > 0.f) ? 1.f : ((ip < 0.f) ? -1.f : 0.f);
            bp = sg*sqrtf(fabsf(ip) + 1e-5f);
        }
        bpv[i] = bp;
        ssum += bp*bp;
    }
    for (int o = 16; o > 0; o >>= 1) ssum += __shfl_xor_sync(0xffffffffu, ssum, o);
    float norm = fmaxf(sqrtf(ssum), 1e-12f);
    float acc = 0.f;
    #pragma unroll
    for (int i = 0; i < 5; ++i) {
        int s = lane + 32*i;
        if (s < cS) acc += bpv[i]*W_out[s];
    }
    for (int o = 16; o > 0; o >>= 1) acc += __shfl_xor_sync(0xffffffffu, acc, o);
    if (lane == 0) out[b] = acc/norm + b_out[0];
}

extern "C" void kernel_launch(void* const* d_in, const int* in_sizes, int n_in,
                              void* d_out, int out_size)
{
    int base = (in_sizes[7] == 1) ? 8 : 7;
    const float* sensor = (const float*)d_in[0];
    const float* img    = (const float*)d_in[1];
    const int*   h1     = (const int*)  d_in[3];
    const int*   h2     = (const int*)  d_in[4];
    const int*   s1     = (const int*)  d_in[5];
    const int*   s2     = (const int*)  d_in[6];
    const float* Wsen   = (const float*)d_in[base+0];
    const float* bsen   = (const float*)d_in[base+1];
    const float* Ws2    = (const float*)d_in[base+2];
    const float* bs2    = (const float*)d_in[base+3];
    const float* Wout   = (const float*)d_in[base+4];
    const float* bout   = (const float*)d_in[base+5];
    const float* tok    = (const float*)d_in[base+6];
    float* out = (float*)d_out;

    static int cfg = 0;
    if (!cfg) {
        cudaFuncSetAttribute(k_conv,      cudaFuncAttributeMaxDynamicSharedMemorySize, 17920*4);
        cudaFuncSetAttribute(k_conv_bias, cudaFuncAttributeMaxDynamicSharedMemorySize, 52992*4);
        cudaFuncSetAttribute(k_quad_mma,  cudaFuncAttributeMaxDynamicSharedMemorySize, SMEM_Q*4);
        cudaFuncSetAttribute(k_quad_bias, cudaFuncAttributeMaxDynamicSharedMemorySize, 27424*4);
        cfg = 1;
    }

    k_init<<<256, 256>>>();
    k_prep<<<dim3(cB, MPAD), 256>>>(img, tok, s1, s2);
    k_se1<<<cB, 256>>>(sensor, Wsen, bsen, h1, h2, bs2, s1, s2);
    k_conv<<<dim3(cB, 8), 256, 17920*4>>>(h2, s2);
    k_conv_bias<<<dim3(cB, 4), 1024, 52992*4>>>(h1, h2, s1, s2);
    k_quad_mma<<<dim3(cB, 6), 256, SMEM_Q*4>>>(h1, h2);
    k_quad_bias<<<dim3(cB, 12, 2), dim3(16, 16), 27424*4>>>(img, h1, h2, tok, s1, s2);
    k_final<<<1, 1024>>>(Ws2, bs2, Wout, bout, out);
}

// round 7
// speedup vs baseline: 1.2513x; 1.2513x over previous
#include <cuda_runtime.h>
#include <cuda_fp16.h>
#include <math.h>

#define cB 32
#define cS 145
#define cC 768
#define cD 8192
#define cSN 64
#define MPAD 160

__device__ float g_se1[cB*cC];
__device__ float g_a1[cB*cD];
__device__ float g_a2[cB*cD];
__device__ float g_u1[cD];
__device__ float g_u2[cD];
__device__ float g_q0[cB*cD];
__device__ float g_q1[cB*cD];
__device__ float g_q2[cD];
__device__ float g_A[3*cB*MPAD];
__device__ int   g_flag;
__device__ __half g_x1h[cB*MPAD*cC];  // fp16 X1t, pair-permuted within 16-k groups
__device__ float  g_x2[cB*MPAD*cC];   // exact X2t

// ---------------- k_init ---------------------------------------------------
__global__ void k_init()
{
    int idx = blockIdx.x*blockDim.x + threadIdx.x;
    int nt  = gridDim.x*blockDim.x;
    for (int i = idx; i < cB*cD; i += nt) { g_a1[i] = 0.f; g_a2[i] = 0.f; }
    for (int i = idx; i < cD;    i += nt) { g_u1[i] = 0.f; g_u2[i] = 0.f; }
    for (int i = idx; i < 3*cB*MPAD; i += nt) g_A[i] = 0.f;
    if (idx == 0) g_flag = 0;
}

// ---------------- k_prep: X1 (fp16, pair-permuted) and X2 (exact) ----------
// pair p = (c>>1)&7 within each 16-k group; stored at slot ((p&3)<<1)|(p>>2)
// so mma fragment pairs (t4, t4+4) are adjacent -> one LDS.64 per 2 regs.
__global__ void k_prep(const float* __restrict__ img, const float* __restrict__ tok,
                       const int* __restrict__ s1, const int* __restrict__ s2)
{
    int b = blockIdx.x, s = blockIdx.y;
    size_t o = (size_t)(b*MPAD + s)*cC;
    for (int c = threadIdx.x; c < cC; c += blockDim.x) {
        float f1 = (float)s1[c], f2 = (float)s2[c];
        float v = 0.f;
        if (s < cS) v = img[((size_t)b*cS + s)*cC + c] + tok[cC + c];
        int p = (c >> 1) & 7;
        int slot = ((p & 3) << 1) | (p >> 2);
        int pos = (c & ~15) | (slot << 1) | (c & 1);
        g_x1h[o + pos] = __float2half_rn(v*f1);
        g_x2[o + c]    = v*f2;
    }
}

// ---------------- k_se1 ----------------------------------------------------
__global__ void k_se1(const float* __restrict__ sensor, const float* __restrict__ Wsen,
                      const float* __restrict__ bsen, const int* __restrict__ h1,
                      const int* __restrict__ h2, const float* __restrict__ b_s2,
                      const int* __restrict__ s1, const int* __restrict__ s2)
{
    int b = blockIdx.x, tid = threadIdx.x;
    __shared__ float ss[cSN];
    if (tid < cSN) ss[tid] = sensor[b*cSN + tid];
    if (b == 0 && tid < cS && b_s2[tid] != 0.f) atomicOr(&g_flag, 1);
    __syncthreads();
    for (int c = tid; c < cC; c += blockDim.x) {
        float acc = bsen[c];
        const float* w = Wsen + c*cSN;
        #pragma unroll 16
        for (int n = 0; n < cSN; ++n) acc += ss[n]*w[n];
        g_se1[b*cC + c] = acc;
        float f1 = (float)s1[c], f2 = (float)s2[c];
        atomicAdd(&g_a1[b*cD + h1[c]], acc*f1);
        atomicAdd(&g_a2[b*cD + h2[c]], acc*f2);
        if (b == 0) { atomicAdd(&g_u1[h1[c]], f1); atomicAdd(&g_u2[h2[c]], f2); }
    }
}

// ---------------- k_conv: 8 d-values per thread ----------------------------
__global__ __launch_bounds__(256) void k_conv(const int* __restrict__ h2,
                                              const int* __restrict__ s2)
{
    extern __shared__ float smc[];
    float*  a1x = smc;
    float2* pt  = (float2*)(smc + 16384);

    int b = blockIdx.x, tid = threadIdx.x;
    for (int j = tid; j < cD; j += 256) {
        float v = g_a1[b*cD + j]; a1x[j] = v; a1x[j + cD] = v;
    }
    for (int c = tid; c < cC; c += 256) {
        pt[c] = make_float2(__int_as_float(cD - h2[c]),
                            g_se1[b*cC + c]*(float)s2[c]);
    }
    __syncthreads();

    int d0 = blockIdx.y*2048 + tid;
    float q[8];
    #pragma unroll
    for (int j = 0; j < 8; ++j) q[j] = 0.f;
    #pragma unroll 2
    for (int c = 0; c < cC; ++c) {
        float2 p = pt[c];
        int base = d0 + __float_as_int(p.x);
        #pragma unroll
        for (int j = 0; j < 8; ++j) q[j] += p.y*a1x[base + j*256];
    }
    float* qo = g_q0 + b*cD + d0;
    #pragma unroll
    for (int j = 0; j < 8; ++j) qo[j*256] = q[j];
}

// ---------------- k_conv_bias ----------------------------------------------
__global__ void k_conv_bias(const int* __restrict__ h1, const int* __restrict__ h2,
                            const int* __restrict__ s1, const int* __restrict__ s2)
{
    extern __shared__ float smc[];
    float* a1x  = smc;
    float* a2x  = smc + 16384;
    float* u1x  = smc + 32768;
    int*   psh2 = (int*)(smc + 49152);
    int*   psh1 = (int*)(smc + 49920);
    float* ps1  = smc + 51456;
    float* ps2  = smc + 52224;

    if (g_flag == 0) return;
    int b = blockIdx.x, tid = threadIdx.x;
    for (int j = tid; j < cD; j += 1024) {
        float v  = g_a1[b*cD + j]; a1x[j] = v;  a1x[j + cD] = v;
        float v2 = g_a2[b*cD + j]; a2x[j] = v2; a2x[j + cD] = v2;
        float v3 = g_u1[j];        u1x[j] = v3; u1x[j + cD] = v3;
    }
    if (tid < cC) {
        psh2[tid] = cD - h2[tid];
        psh1[tid] = cD - h1[tid];
        ps1[tid]  = (float)s1[tid];
        ps2[tid]  = (float)s2[tid];
    }
    __syncthreads();

    int d0 = blockIdx.y*2048 + tid, d1 = d0 + 1024;
    float q1a = 0.f, q1b = 0.f, q2a = 0.f, q2b = 0.f;
    for (int c = 0; c < cC; ++c) {
        int s2v = psh2[c], s1v = psh1[c];
        float f1 = ps1[c], f2 = ps2[c];
        q1a += f2*a1x[d0 + s2v] + f1*a2x[d0 + s1v];
        q1b += f2*a1x[d1 + s2v] + f1*a2x[d1 + s1v];
        q2a += f2*u1x[d0 + s2v];
        q2b += f2*u1x[d1 + s2v];
    }
    g_q1[b*cD + d0] = q1a; g_q1[b*cD + d1] = q1b;
    if (b == 0) { g_q2[d0] = q2a; g_q2[d1] = q2b; }
}

// ---------------- k_quad_mma: fp16 m16n8k16, M=160 x N=64 ------------------
// 8 warps = 2(wm) x 4(wn); warp tile 80x16; K-chunk 64 (4 mma k-steps), 12 iters.
#define SQH_OFF  0                     // 8192 halves = 4096 floats
#define SH1_OFF  4096                  // 768 ints
#define SRED_OFF (SH1_OFF + 768)       // 160
#define SA_OFF   (SRED_OFF + 160)      // 160 rows x 36 u32
#define SB_OFF   (SA_OFF + 160*36)     // 64 rows x 36 u32
#define SMEM_Q   (SB_OFF + 64*36)      // 13088 floats = 52352 B

__global__ __launch_bounds__(256) void k_quad_mma(const int* __restrict__ h1,
                                                  const int* __restrict__ h2)
{
    extern __shared__ float sm[];
    unsigned short* sQh = (unsigned short*)sm;
    int*      sH1L = (int*)(sm + SH1_OFF);
    float*    sRed = sm + SRED_OFF;
    unsigned* sA   = (unsigned*)(sm + SA_OFF);
    unsigned* sB   = (unsigned*)(sm + SB_OFF);

    int b = blockIdx.x, c2base = blockIdx.y*64;
    int tid = threadIdx.x, lane = tid & 31, warp = tid >> 5;
    int wm = warp & 1, wn = warp >> 1;
    int t4 = lane & 3, qr = lane >> 2;

    const float* qsrc = g_q0 + b*cD;
    for (int j = tid; j < cD; j += 256)
        sQh[j] = __half_as_ushort(__float2half_rn(qsrc[j]));
    // h1 in A-layout order: invert the pair permutation
    for (int i = tid; i < cC; i += 256) {
        int jj = (i >> 1) & 7;
        int p = (jj >> 1) | ((jj & 1) << 2);
        sH1L[i] = h1[(i & ~15) | (p << 1) | (i & 1)];
    }
    if (tid < MPAD) sRed[tid] = 0.f;
    int gn = tid >> 2, gq = tid & 3;
    int h2v = h2[c2base + gn];
    __syncthreads();

    const __half* x1p = g_x1h + (size_t)b*MPAD*cC;

    float acc[5][2][4];
    #pragma unroll
    for (int mi = 0; mi < 5; ++mi)
        #pragma unroll
        for (int ni = 0; ni < 2; ++ni)
            #pragma unroll
            for (int j = 0; j < 4; ++j) acc[mi][ni][j] = 0.f;

    for (int r = 0; r < 12; ++r) {
        // stage A: 160 rows x 64 halves (layout already permuted in global)
        #pragma unroll
        for (int i = 0; i < 5; ++i) {
            int e = tid + i*256;
            int row = e >> 3, kq = e & 7;
            uint4 v = *(const uint4*)(x1p + (size_t)row*cC + r*64 + kq*8);
            *(uint4*)(sA + row*36 + kq*4) = v;
        }
        // gather B: 64 n x 32 pairs; each thread (n = tid>>2, 8 pairs)
        {
            const int* hL = sH1L + r*64;
            #pragma unroll
            for (int j = 0; j < 8; ++j) {
                int jj = gq*8 + j;
                unsigned u0 = sQh[(hL[2*jj]     + h2v) & (cD - 1)];
                unsigned u1 = sQh[(hL[2*jj + 1] + h2v) & (cD - 1)];
                sB[gn*36 + jj] = u0 | (u1 << 16);
            }
        }
        __syncthreads();

        #pragma unroll
        for (int ks = 0; ks < 4; ++ks) {
            uint2 bfr[2];
            #pragma unroll
            for (int ni = 0; ni < 2; ++ni) {
                int n0 = wn*16 + ni*8 + qr;
                bfr[ni] = *(const uint2*)(sB + n0*36 + ks*8 + 2*t4);
            }
            #pragma unroll
            for (int mi = 0; mi < 5; ++mi) {
                int r0 = wm*80 + mi*16 + qr;
                uint2 aA = *(const uint2*)(sA + r0*36 + ks*8 + 2*t4);
                uint2 aB = *(const uint2*)(sA + (r0 + 8)*36 + ks*8 + 2*t4);
                #pragma unroll
                for (int ni = 0; ni < 2; ++ni) {
                    asm volatile(
                        "mma.sync.aligned.m16n8k16.row.col.f32.f16.f16.f32 "
                        "{%0,%1,%2,%3}, {%4,%5,%6,%7}, {%8,%9}, {%0,%1,%2,%3};"
                        : "+f"(acc[mi][ni][0]), "+f"(acc[mi][ni][1]),
                          "+f"(acc[mi][ni][2]), "+f"(acc[mi][ni][3])
                        : "r"(aA.x), "r"(aB.x), "r"(aA.y), "r"(aB.y),
                          "r"(bfr[ni].x), "r"(bfr[ni].y));
                }
            }
        }
        __syncthreads();
    }

    // epilogue: fold with exact fp32 X2
    const float* x2p = g_x2 + (size_t)b*MPAD*cC;
    #pragma unroll
    for (int mi = 0; mi < 5; ++mi) {
        int r0 = wm*80 + mi*16 + qr;
        int r1 = r0 + 8;
        float s0 = 0.f, s1v = 0.f;
        #pragma unroll
        for (int ni = 0; ni < 2; ++ni) {
            int col = c2base + wn*16 + ni*8 + 2*t4;
            float2 xa = *(const float2*)(x2p + (size_t)r0*cC + col);
            float2 xb = *(const float2*)(x2p + (size_t)r1*cC + col);
            s0  += acc[mi][ni][0]*xa.x + acc[mi][ni][1]*xa.y;
            s1v += acc[mi][ni][2]*xb.x + acc[mi][ni][3]*xb.y;
        }
        atomicAdd(&sRed[r0], s0);
        atomicAdd(&sRed[r1], s1v);
    }
    __syncthreads();
    if (tid < MPAD) atomicAdd(&g_A[b*MPAD + tid], sRed[tid]);
}

// ---------------- scalar quad for bias terms (z=1,2) -----------------------
__global__ __launch_bounds__(256) void k_quad_bias(const float* __restrict__ img,
                                                   const int* __restrict__ h1,
                                                   const int* __restrict__ h2,
                                                   const float* __restrict__ tok,
                                                   const int* __restrict__ s1,
                                                   const int* __restrict__ s2)
{
    extern __shared__ float smem[];
    float* sQ  = smem;
    float* sX1 = smem + 8192;
    float* sX2 = smem + 13344;
    int*   sH1 = (int*)(smem + 23584);
    float* sS1 = smem + 24352;
    float* sS2 = smem + 25120;
    float* sTk = smem + 25888;

    if (g_flag == 0) return;
    int z = blockIdx.z + 1;
    int b = blockIdx.x, c2base = blockIdx.y*64;
    int tx = threadIdx.x, ty = threadIdx.y, tid = ty*16 + tx;

    const float* qsrc = (z == 1) ? (g_q1 + b*cD) : g_q2;
    for (int j = tid; j < cD; j += 256) sQ[j] = qsrc[j];
    for (int j = tid; j < cC; j += 256) {
        sH1[j] = h1[j];
        sS1[j] = (float)s1[j]; sS2[j] = (float)s2[j];
        sTk[j] = tok[cC + j];
    }
    __syncthreads();

    for (int e = tid; e < MPAD*64; e += 256) {
        int c2l = e & 63, s = e >> 6;
        int c2 = c2base + c2l;
        float v = 0.f;
        if (s < cS) v = (img[(b*cS + s)*cC + c2] + sTk[c2])*sS2[c2];
        sX2[s*64 + c2l] = v;
    }

    int h2r[4];
    #pragma unroll
    for (int n = 0; n < 4; ++n) h2r[n] = h2[c2base + tx + 16*n];

    float acc[10][4];
    #pragma unroll
    for (int m = 0; m < 10; ++m)
        #pragma unroll
        for (int n = 0; n < 4; ++n) acc[m][n] = 0.f;

    for (int k0 = 0; k0 < cC; k0 += 32) {
        __syncthreads();
        #pragma unroll
        for (int i = 0; i < 20; ++i) {
            int e = tid + i*256;
            int kt = e & 31, s = e >> 5;
            int c1 = k0 + kt;
            float v = 0.f;
            if (s < cS) v = (img[(b*cS + s)*cC + c1] + sTk[c1])*sS1[c1];
            sX1[kt*161 + s] = v;
        }
        __syncthreads();
        #pragma unroll 8
        for (int kt = 0; kt < 32; ++kt) {
            int h1v = sH1[k0 + kt];
            float x1r[10];
            #pragma unroll
            for (int m = 0; m < 10; ++m) x1r[m] = sX1[kt*161 + ty + 16*m];
            float qv[4];
            #pragma unroll
            for (int n = 0; n < 4; ++n) qv[n] = sQ[(h1v + h2r[n]) & (cD - 1)];
            #pragma unroll
            for (int m = 0; m < 10; ++m)
                #pragma unroll
                for (int n = 0; n < 4; ++n)
                    acc[m][n] += x1r[m]*qv[n];
        }
    }

    #pragma unroll
    for (int m = 0; m < 10; ++m) {
        int s = ty + 16*m;
        float al = 0.f;
        #pragma unroll
        for (int n = 0; n < 4; ++n) al += acc[m][n]*sX2[s*64 + tx + 16*n];
        atomicAdd(&g_A[(z*cB + b)*MPAD + s], al);
    }
}

// ---------------- k_final --------------------------------------------------
__global__ void k_final(const float* __restrict__ W_s2, const float* __restrict__ b_s2,
                        const float* __restrict__ W_out, const float* __restrict__ b_out,
                        float* __restrict__ out)
{
    int tid = threadIdx.x;
    int b = tid >> 5, lane = tid & 31;
    float bpv[5]; float ssum = 0.f;
    #pragma unroll
    for (int i = 0; i < 5; ++i) {
        int s = lane + 32*i;
        float bp = 0.f;
        if (s < cS) {
            float w = W_s2[s], be = b_s2[s];
            float ip = w*w*g_A[b*MPAD + s]
                     + w*be*g_A[(cB + b)*MPAD + s]
                     + be*be*g_A[(2*cB + b)*MPAD + s];
            float sg = (ip > 0.f) ? 1.f : ((ip < 0.f) ? -1.f : 0.f);
            bp = sg*sqrtf(fabsf(ip) + 1e-5f);
        }
        bpv[i] = bp;
        ssum += bp*bp;
    }
    for (int o = 16; o > 0; o >>= 1) ssum += __shfl_xor_sync(0xffffffffu, ssum, o);
    float norm = fmaxf(sqrtf(ssum), 1e-12f);
    float acc = 0.f;
    #pragma unroll
    for (int i = 0; i < 5; ++i) {
        int s = lane + 32*i;
        if (s < cS) acc += bpv[i]*W_out[s];
    }
    for (int o = 16; o > 0; o >>= 1) acc += __shfl_xor_sync(0xffffffffu, acc, o);
    if (lane == 0) out[b] = acc/norm + b_out[0];
}

extern "C" void kernel_launch(void* const* d_in, const int* in_sizes, int n_in,
                              void* d_out, int out_size)
{
    int base = (in_sizes[7] == 1) ? 8 : 7;
    const float* sensor = (const float*)d_in[0];
    const float* img    = (const float*)d_in[1];
    const int*   h1     = (const int*)  d_in[3];
    const int*   h2     = (const int*)  d_in[4];
    const int*   s1     = (const int*)  d_in[5];
    const int*   s2     = (const int*)  d_in[6];
    const float* Wsen   = (const float*)d_in[base+0];
    const float* bsen   = (const float*)d_in[base+1];
    const float* Ws2    = (const float*)d_in[base+2];
    const float* bs2    = (const float*)d_in[base+3];
    const float* Wout   = (const float*)d_in[base+4];
    const float* bout   = (const float*)d_in[base+5];
    const float* tok    = (const float*)d_in[base+6];
    float* out = (float*)d_out;

    static int cfg = 0;
    if (!cfg) {
        cudaFuncSetAttribute(k_conv,      cudaFuncAttributeMaxDynamicSharedMemorySize, 17920*4);
        cudaFuncSetAttribute(k_conv_bias, cudaFuncAttributeMaxDynamicSharedMemorySize, 52992*4);
        cudaFuncSetAttribute(k_quad_mma,  cudaFuncAttributeMaxDynamicSharedMemorySize, SMEM_Q*4);
        cudaFuncSetAttribute(k_quad_bias, cudaFuncAttributeMaxDynamicSharedMemorySize, 27424*4);
        cfg = 1;
    }

    k_init<<<256, 256>>>();
    k_prep<<<dim3(cB, MPAD), 256>>>(img, tok, s1, s2);
    k_se1<<<cB, 256>>>(sensor, Wsen, bsen, h1, h2, bs2, s1, s2);
    k_conv<<<dim3(cB, 4), 256, 17920*4>>>(h2, s2);
    k_conv_bias<<<dim3(cB, 4), 1024, 52992*4>>>(h1, h2, s1, s2);
    k_quad_mma<<<dim3(cB, 12), 256, SMEM_Q*4>>>(h1, h2);
    k_quad_bias<<<dim3(cB, 12, 2), dim3(16, 16), 27424*4>>>(img, h1, h2, tok, s1, s2);
    k_final<<<1, 1024>>>(Ws2, bs2, Wout, bout, out);
}

// round 9
// speedup vs baseline: 1.3337x; 1.0659x over previous
#include <cuda_runtime.h>
#include <cuda_fp16.h>
#include <math.h>

#define cB 32
#define cS 145
#define cC 768
#define cD 8192
#define cSN 64
#define MPAD 160

__device__ float g_se1[cB*cC];
__device__ float g_a1[cB*cD];
__device__ float g_a2[cB*cD];
__device__ float g_u1[cD];
__device__ float g_u2[cD];
__device__ float g_q0[cB*cD];
__device__ float g_q1[cB*cD];
__device__ float g_q2[cD];
__device__ float g_A[3*cB*MPAD];
__device__ int   g_flag;
__device__ __half g_x1h[cB*MPAD*cC];  // fp16 X1t, pair-permuted within 16-k groups
__device__ float  g_x2[cB*MPAD*cC];   // exact X2t

// ---------------- k_prep: X1 (fp16, pair-permuted) and X2 (exact) ----------
__global__ void k_prep(const float* __restrict__ img, const float* __restrict__ tok,
                       const int* __restrict__ s1, const int* __restrict__ s2)
{
    int b = blockIdx.x, s = blockIdx.y;
    size_t o = (size_t)(b*MPAD + s)*cC;
    for (int c = threadIdx.x; c < cC; c += blockDim.x) {
        float f1 = (float)s1[c], f2 = (float)s2[c];
        float v = 0.f;
        if (s < cS) v = img[((size_t)b*cS + s)*cC + c] + tok[cC + c];
        int p = (c >> 1) & 7;
        int slot = ((p & 3) << 1) | (p >> 2);
        int pos = (c & ~15) | (slot << 1) | (c & 1);
        g_x1h[o + pos] = __float2half_rn(v*f1);
        g_x2[o + c]    = v*f2;
    }
}

// ---------------- k_se1: fused zero-init + sensor GEMV + scatter -----------
__global__ void k_se1(const float* __restrict__ sensor, const float* __restrict__ Wsen,
                      const float* __restrict__ bsen, const int* __restrict__ h1,
                      const int* __restrict__ h2, const float* __restrict__ b_s2,
                      const int* __restrict__ s1, const int* __restrict__ s2)
{
    int b = blockIdx.x, tid = threadIdx.x;
    __shared__ float ss[cSN];
    __shared__ int sflag;

    for (int j = tid; j < cD; j += 256) { g_a1[b*cD + j] = 0.f; g_a2[b*cD + j] = 0.f; }
    if (b == 0) for (int j = tid; j < cD; j += 256) { g_u1[j] = 0.f; g_u2[j] = 0.f; }
    #pragma unroll
    for (int z = 0; z < 3; ++z)
        for (int j = tid; j < MPAD; j += 256) g_A[(z*cB + b)*MPAD + j] = 0.f;

    if (tid == 0) sflag = 0;
    if (tid < cSN) ss[tid] = sensor[b*cSN + tid];
    __syncthreads();
    if (b == 0 && tid < cS && b_s2[tid] != 0.f) atomicOr(&sflag, 1);

    for (int c = tid; c < cC; c += 256) {
        float acc = bsen[c];
        const float* w = Wsen + c*cSN;
        #pragma unroll 16
        for (int n = 0; n < cSN; ++n) acc += ss[n]*w[n];
        g_se1[b*cC + c] = acc;
        float f1 = (float)s1[c], f2 = (float)s2[c];
        atomicAdd(&g_a1[b*cD + h1[c]], acc*f1);
        atomicAdd(&g_a2[b*cD + h2[c]], acc*f2);
        if (b == 0) { atomicAdd(&g_u1[h1[c]], f1); atomicAdd(&g_u2[h2[c]], f2); }
    }
    if (b == 0) {
        __syncthreads();
        if (tid == 0) g_flag = sflag;
    }
}

// ---------------- k_conv: half2-packed a1, fp32 accumulation ---------------
// a1p[j] = (a1[j&8191], a1[(j+512)&8191]); one LDS.32 serves d and d+512.
// grid (cB, 8), 256 threads; thread covers d0, d0+256, d0+512, d0+768.
#define CONV_SMEM (16384*4 + 768*8)   // 71680 B
__global__ __launch_bounds__(256) void k_conv(const int* __restrict__ h2,
                                              const int* __restrict__ s2)
{
    extern __shared__ float smc[];
    __half2* a1p = (__half2*)smc;             // 16384 entries
    float2*  pt  = (float2*)(smc + 16384);    // 768 entries (shift-as-float, pv)

    int b = blockIdx.x, tid = threadIdx.x;
    const float* ga = g_a1 + b*cD;
    for (int j = tid; j < 16384; j += 256) {
        float v0 = ga[j & (cD - 1)];
        float v1 = ga[(j + 512) & (cD - 1)];
        a1p[j] = __floats2half2_rn(v0, v1);
    }
    for (int c = tid; c < cC; c += 256) {
        float2 e;
        e.x = __int_as_float(cD - h2[c]);
        e.y = g_se1[b*cC + c]*(float)s2[c];
        pt[c] = e;
    }
    __syncthreads();

    int d0 = blockIdx.y*1024 + tid;           // lanes consecutive -> conflict-free
    int i1 = d0 + 256;
    float q00 = 0.f, q01 = 0.f, q10 = 0.f, q11 = 0.f;
    #pragma unroll 4
    for (int c = 0; c < cC; ++c) {
        float2 p = pt[c];
        int sh = __float_as_int(p.x);
        float2 va = __half22float2(a1p[d0 + sh]);
        float2 vb = __half22float2(a1p[i1 + sh]);
        q00 += p.y*va.x; q01 += p.y*va.y;
        q10 += p.y*vb.x; q11 += p.y*vb.y;
    }
    float* qo = g_q0 + b*cD;
    qo[d0]       = q00;
    qo[d0 + 512] = q01;
    qo[d0 + 256] = q10;
    qo[d0 + 768] = q11;
}

// ---------------- k_conv_bias ----------------------------------------------
__global__ void k_conv_bias(const int* __restrict__ h1, const int* __restrict__ h2,
                            const int* __restrict__ s1, const int* __restrict__ s2)
{
    extern __shared__ float smc[];
    float* a1x  = smc;
    float* a2x  = smc + 16384;
    float* u1x  = smc + 32768;
    int*   psh2 = (int*)(smc + 49152);
    int*   psh1 = (int*)(smc + 49920);
    float* ps1  = smc + 51456;
    float* ps2  = smc + 52224;

    if (g_flag == 0) return;
    int b = blockIdx.x, tid = threadIdx.x;
    for (int j = tid; j < cD; j += 1024) {
        float v  = g_a1[b*cD + j]; a1x[j] = v;  a1x[j + cD] = v;
        float v2 = g_a2[b*cD + j]; a2x[j] = v2; a2x[j + cD] = v2;
        float v3 = g_u1[j];        u1x[j] = v3; u1x[j + cD] = v3;
    }
    if (tid < cC) {
        psh2[tid] = cD - h2[tid];
        psh1[tid] = cD - h1[tid];
        ps1[tid]  = (float)s1[tid];
        ps2[tid]  = (float)s2[tid];
    }
    __syncthreads();

    int d0 = blockIdx.y*2048 + tid, d1 = d0 + 1024;
    float q1a = 0.f, q1b = 0.f, q2a = 0.f, q2b = 0.f;
    for (int c = 0; c < cC; ++c) {
        int s2v = psh2[c], s1v = psh1[c];
        float f1 = ps1[c], f2 = ps2[c];
        q1a += f2*a1x[d0 + s2v] + f1*a2x[d0 + s1v];
        q1b += f2*a1x[d1 + s2v] + f1*a2x[d1 + s1v];
        q2a += f2*u1x[d0 + s2v];
        q2b += f2*u1x[d1 + s2v];
    }
    g_q1[b*cD + d0] = q1a; g_q1[b*cD + d1] = q1b;
    if (b == 0) { g_q2[d0] = q2a; g_q2[d1] = q2b; }
}

// ---------------- k_quad_mma: fp16 m16n8k16, M=160 x N=64 ------------------
#define SQH_OFF  0
#define SH1_OFF  4096
#define SRED_OFF (SH1_OFF + 768)
#define SA_OFF   (SRED_OFF + 160)
#define SB_OFF   (SA_OFF + 160*36)
#define SMEM_Q   (SB_OFF + 64*36)

__global__ __launch_bounds__(256) void k_quad_mma(const int* __restrict__ h1,
                                                  const int* __restrict__ h2)
{
    extern __shared__ float sm[];
    unsigned short* sQh = (unsigned short*)sm;
    int*      sH1L = (int*)(sm + SH1_OFF);
    float*    sRed = sm + SRED_OFF;
    unsigned* sA   = (unsigned*)(sm + SA_OFF);
    unsigned* sB   = (unsigned*)(sm + SB_OFF);

    int b = blockIdx.x, c2base = blockIdx.y*64;
    int tid = threadIdx.x, lane = tid & 31, warp = tid >> 5;
    int wm = warp & 1, wn = warp >> 1;
    int t4 = lane & 3, qr = lane >> 2;

    const float* qsrc = g_q0 + b*cD;
    for (int j = tid; j < cD; j += 256)
        sQh[j] = __half_as_ushort(__float2half_rn(qsrc[j]));
    for (int i = tid; i < cC; i += 256) {
        int jj = (i >> 1) & 7;
        int p = (jj >> 1) | ((jj & 1) << 2);
        sH1L[i] = h1[(i & ~15) | (p << 1) | (i & 1)];
    }
    if (tid < MPAD) sRed[tid] = 0.f;
    int gn = tid >> 2, gq = tid & 3;
    int h2v = h2[c2base + gn];
    __syncthreads();

    const __half* x1p = g_x1h + (size_t)b*MPAD*cC;

    float acc[5][2][4];
    #pragma unroll
    for (int mi = 0; mi < 5; ++mi)
        #pragma unroll
        for (int ni = 0; ni < 2; ++ni)
            #pragma unroll
            for (int j = 0; j < 4; ++j) acc[mi][ni][j] = 0.f;

    for (int r = 0; r < 12; ++r) {
        #pragma unroll
        for (int i = 0; i < 5; ++i) {
            int e = tid + i*256;
            int row = e >> 3, kq = e & 7;
            uint4 v = *(const uint4*)(x1p + (size_t)row*cC + r*64 + kq*8);
            *(uint4*)(sA + row*36 + kq*4) = v;
        }
        {
            const int* hL = sH1L + r*64;
            #pragma unroll
            for (int j = 0; j < 8; ++j) {
                int jj = gq*8 + j;
                unsigned u0 = sQh[(hL[2*jj]     + h2v) & (cD - 1)];
                unsigned u1 = sQh[(hL[2*jj + 1] + h2v) & (cD - 1)];
                sB[gn*36 + jj] = u0 | (u1 << 16);
            }
        }
        __syncthreads();

        #pragma unroll
        for (int ks = 0; ks < 4; ++ks) {
            uint2 bfr[2];
            #pragma unroll
            for (int ni = 0; ni < 2; ++ni) {
                int n0 = wn*16 + ni*8 + qr;
                bfr[ni] = *(const uint2*)(sB + n0*36 + ks*8 + 2*t4);
            }
            #pragma unroll
            for (int mi = 0; mi < 5; ++mi) {
                int r0 = wm*80 + mi*16 + qr;
                uint2 aA = *(const uint2*)(sA + r0*36 + ks*8 + 2*t4);
                uint2 aB = *(const uint2*)(sA + (r0 + 8)*36 + ks*8 + 2*t4);
                #pragma unroll
                for (int ni = 0; ni < 2; ++ni) {
                    asm volatile(
                        "mma.sync.aligned.m16n8k16.row.col.f32.f16.f16.f32 "
                        "{%0,%1,%2,%3}, {%4,%5,%6,%7}, {%8,%9}, {%0,%1,%2,%3};"
                        : "+f"(acc[mi][ni][0]), "+f"(acc[mi][ni][1]),
                          "+f"(acc[mi][ni][2]), "+f"(acc[mi][ni][3])
                        : "r"(aA.x), "r"(aB.x), "r"(aA.y), "r"(aB.y),
                          "r"(bfr[ni].x), "r"(bfr[ni].y));
                }
            }
        }
        __syncthreads();
    }

    const float* x2p = g_x2 + (size_t)b*MPAD*cC;
    #pragma unroll
    for (int mi = 0; mi < 5; ++mi) {
        int r0 = wm*80 + mi*16 + qr;
        int r1 = r0 + 8;
        float s0 = 0.f, s1v = 0.f;
        #pragma unroll
        for (int ni = 0; ni < 2; ++ni) {
            int col = c2base + wn*16 + ni*8 + 2*t4;
            float2 xa = *(const float2*)(x2p + (size_t)r0*cC + col);
            float2 xb = *(const float2*)(x2p + (size_t)r1*cC + col);
            s0  += acc[mi][ni][0]*xa.x + acc[mi][ni][1]*xa.y;
            s1v += acc[mi][ni][2]*xb.x + acc[mi][ni][3]*xb.y;
        }
        atomicAdd(&sRed[r0], s0);
        atomicAdd(&sRed[r1], s1v);
    }
    __syncthreads();
    if (tid < MPAD) atomicAdd(&g_A[b*MPAD + tid], sRed[tid]);
}

// ---------------- scalar quad for bias terms (z=1,2) -----------------------
__global__ __launch_bounds__(256) void k_quad_bias(const float* __restrict__ img,
                                                   const int* __restrict__ h1,
                                                   const int* __restrict__ h2,
                                                   const float* __restrict__ tok,
                                                   const int* __restrict__ s1,
                                                   const int* __restrict__ s2)
{
    extern __shared__ float smem[];
    float* sQ  = smem;
    float* sX1 = smem + 8192;
    float* sX2 = smem + 13344;
    int*   sH1 = (int*)(smem + 23584);
    float* sS1 = smem + 24352;
    float* sS2 = smem + 25120;
    float* sTk = smem + 25888;

    if (g_flag == 0) return;
    int z = blockIdx.z + 1;
    int b = blockIdx.x, c2base = blockIdx.y*64;
    int tx = threadIdx.x, ty = threadIdx.y, tid = ty*16 + tx;

    const float* qsrc = (z == 1) ? (g_q1 + b*cD) : g_q2;
    for (int j = tid; j < cD; j += 256) sQ[j] = qsrc[j];
    for (int j = tid; j < cC; j += 256) {
        sH1[j] = h1[j];
        sS1[j] = (float)s1[j]; sS2[j] = (float)s2[j];
        sTk[j] = tok[cC + j];
    }
    __syncthreads();

    for (int e = tid; e < MPAD*64; e += 256) {
        int c2l = e & 63, s = e >> 6;
        int c2 = c2base + c2l;
        float v = 0.f;
        if (s < cS) v = (img[(b*cS + s)*cC + c2] + sTk[c2])*sS2[c2];
        sX2[s*64 + c2l] = v;
    }

    int h2r[4];
    #pragma unroll
    for (int n = 0; n < 4; ++n) h2r[n] = h2[c2base + tx + 16*n];

    float acc[10][4];
    #pragma unroll
    for (int m = 0; m < 10; ++m)
        #pragma unroll
        for (int n = 0; n < 4; ++n) acc[m][n] = 0.f;

    for (int k0 = 0; k0 < cC; k0 += 32) {
        __syncthreads();
        #pragma unroll
        for (int i = 0; i < 20; ++i) {
            int e = tid + i*256;
            int kt = e & 31, s = e >> 5;
            int c1 = k0 + kt;
            float v = 0.f;
            if (s < cS) v = (img[(b*cS + s)*cC + c1] + sTk[c1])*sS1[c1];
            sX1[kt*161 + s] = v;
        }
        __syncthreads();
        #pragma unroll 8
        for (int kt = 0; kt < 32; ++kt) {
            int h1v = sH1[k0 + kt];
            float x1r[10];
            #pragma unroll
            for (int m = 0; m < 10; ++m) x1r[m] = sX1[kt*161 + ty + 16*m];
            float qv[4];
            #pragma unroll
            for (int n = 0; n < 4; ++n) qv[n] = sQ[(h1v + h2r[n]) & (cD - 1)];
            #pragma unroll
            for (int m = 0; m < 10; ++m)
                #pragma unroll
                for (int n = 0; n < 4; ++n)
                    acc[m][n] += x1r[m]*qv[n];
        }
    }

    #pragma unroll
    for (int m = 0; m < 10; ++m) {
        int s = ty + 16*m;
        float al = 0.f;
        #pragma unroll
        for (int n = 0; n < 4; ++n) al += acc[m][n]*sX2[s*64 + tx + 16*n];
        atomicAdd(&g_A[(z*cB + b)*MPAD + s], al);
    }
}

// ---------------- k_final --------------------------------------------------
__global__ void k_final(const float* __restrict__ W_s2, const float* __restrict__ b_s2,
                        const float* __restrict__ W_out, const float* __restrict__ b_out,
                        float* __restrict__ out)
{
    int tid = threadIdx.x;
    int b = tid >> 5, lane = tid & 31;
    float bpv[5]; float ssum = 0.f;
    #pragma unroll
    for (int i = 0; i < 5; ++i) {
        int s = lane + 32*i;
        float bp = 0.f;
        if (s < cS) {
            float w = W_s2[s], be = b_s2[s];
            float ip = w*w*g_A[b*MPAD + s]
                     + w*be*g_A[(cB + b)*MPAD + s]
                     + be*be*g_A[(2*cB + b)*MPAD + s];
            float sg = (ip > 0.f) ? 1.f : ((ip < 0.f) ? -1.f : 0.f);
            bp = sg*sqrtf(fabsf(ip) + 1e-5f);
        }
        bpv[i] = bp;
        ssum += bp*bp;
    }
    for (int o = 16; o > 0; o >>= 1) ssum += __shfl_xor_sync(0xffffffffu, ssum, o);
    float norm = fmaxf(sqrtf(ssum), 1e-12f);
    float acc = 0.f;
    #pragma unroll
    for (int i = 0; i < 5; ++i) {
        int s = lane + 32*i;
        if (s < cS) acc += bpv[i]*W_out[s];
    }
    for (int o = 16; o > 0; o >>= 1) acc += __shfl_xor_sync(0xffffffffu, acc, o);
    if (lane == 0) out[b] = acc/norm + b_out[0];
}

extern "C" void kernel_launch(void* const* d_in, const int* in_sizes, int n_in,
                              void* d_out, int out_size)
{
    int base = (in_sizes[7] == 1) ? 8 : 7;
    const float* sensor = (const float*)d_in[0];
    const float* img    = (const float*)d_in[1];
    const int*   h1     = (const int*)  d_in[3];
    const int*   h2     = (const int*)  d_in[4];
    const int*   s1     = (const int*)  d_in[5];
    const int*   s2     = (const int*)  d_in[6];
    const float* Wsen   = (const float*)d_in[base+0];
    const float* bsen   = (const float*)d_in[base+1];
    const float* Ws2    = (const float*)d_in[base+2];
    const float* bs2    = (const float*)d_in[base+3];
    const float* Wout   = (const float*)d_in[base+4];
    const float* bout   = (const float*)d_in[base+5];
    const float* tok    = (const float*)d_in[base+6];
    float* out = (float*)d_out;

    static int cfg = 0;
    if (!cfg) {
        cudaFuncSetAttribute(k_conv,      cudaFuncAttributeMaxDynamicSharedMemorySize, CONV_SMEM);
        cudaFuncSetAttribute(k_conv_bias, cudaFuncAttributeMaxDynamicSharedMemorySize, 52992*4);
        cudaFuncSetAttribute(k_quad_mma,  cudaFuncAttributeMaxDynamicSharedMemorySize, SMEM_Q*4);
        cudaFuncSetAttribute(k_quad_bias, cudaFuncAttributeMaxDynamicSharedMemorySize, 27424*4);
        cfg = 1;
    }

    k_prep<<<dim3(cB, MPAD), 256>>>(img, tok, s1, s2);
    k_se1<<<cB, 256>>>(sensor, Wsen, bsen, h1, h2, bs2, s1, s2);
    k_conv<<<dim3(cB, 8), 256, CONV_SMEM>>>(h2, s2);
    k_conv_bias<<<dim3(cB, 4), 1024, 52992*4>>>(h1, h2, s1, s2);
    k_quad_mma<<<dim3(cB, 12), 256, SMEM_Q*4>>>(h1, h2);
    k_quad_bias<<<dim3(cB, 12, 2), dim3(16, 16), 27424*4>>>(img, h1, h2, tok, s1, s2);
    k_final<<<1, 1024>>>(Ws2, bs2, Wout, bout, out);
}

// round 10
// speedup vs baseline: 1.3774x; 1.0328x over previous
#include <cuda_runtime.h>
#include <cuda_fp16.h>
#include <math.h>

#define cB 32
#define cS 145
#define cC 768
#define cD 8192
#define cSN 64
#define MPAD 160

__device__ float g_se1[cB*cC];
__device__ float g_a1[cB*cD];
__device__ float g_a2[cB*cD];
__device__ float g_u1[cD];
__device__ float g_u2[cD];
__device__ float g_q0[cB*cD];
__device__ float g_q1[cB*cD];
__device__ float g_q2[cD];
__device__ float g_A[3*cB*MPAD];
__device__ int   g_flag;
__device__ __half g_x1h[cB*MPAD*cC];  // fp16 X1t, pair-permuted; pad rows stay 0
__device__ float  g_x2[cB*MPAD*cC];   // exact X2t; pad rows stay 0

// ---------------- k_prep_se1: fused prep (y<145) + se1 (y==145) ------------
__global__ void k_prep_se1(const float* __restrict__ img, const float* __restrict__ tok,
                           const int* __restrict__ s1, const int* __restrict__ s2,
                           const float* __restrict__ sensor, const float* __restrict__ Wsen,
                           const float* __restrict__ bsen, const int* __restrict__ h1,
                           const int* __restrict__ h2, const float* __restrict__ b_s2)
{
    int b = blockIdx.x, y = blockIdx.y, tid = threadIdx.x;
    if (y < cS) {
        // prep one s-row: X1 fp16 (pair-permuted), X2 exact
        size_t o = (size_t)(b*MPAD + y)*cC;
        const float* ir = img + ((size_t)b*cS + y)*cC;
        for (int c = tid; c < cC; c += 256) {
            float f1 = (float)s1[c], f2 = (float)s2[c];
            float v = ir[c] + tok[cC + c];
            int p = (c >> 1) & 7;
            int slot = ((p & 3) << 1) | (p >> 2);
            int pos = (c & ~15) | (slot << 1) | (c & 1);
            g_x1h[o + pos] = __float2half_rn(v*f1);
            g_x2[o + c]    = v*f2;
        }
        return;
    }
    // se1 branch: zero scratch, flag, sensor GEMV + sketch scatter
    __shared__ float ss[cSN];
    __shared__ int sflag;
    for (int j = tid; j < cD; j += 256) { g_a1[b*cD + j] = 0.f; g_a2[b*cD + j] = 0.f; }
    if (b == 0) for (int j = tid; j < cD; j += 256) { g_u1[j] = 0.f; g_u2[j] = 0.f; }
    #pragma unroll
    for (int z = 0; z < 3; ++z)
        for (int j = tid; j < MPAD; j += 256) g_A[(z*cB + b)*MPAD + j] = 0.f;

    if (tid == 0) sflag = 0;
    if (tid < cSN) ss[tid] = sensor[b*cSN + tid];
    __syncthreads();
    if (b == 0 && tid < cS && b_s2[tid] != 0.f) atomicOr(&sflag, 1);

    for (int c = tid; c < cC; c += 256) {
        float acc = bsen[c];
        const float* w = Wsen + c*cSN;
        #pragma unroll 16
        for (int n = 0; n < cSN; ++n) acc += ss[n]*w[n];
        g_se1[b*cC + c] = acc;
        float f1 = (float)s1[c], f2 = (float)s2[c];
        atomicAdd(&g_a1[b*cD + h1[c]], acc*f1);
        atomicAdd(&g_a2[b*cD + h2[c]], acc*f2);
        if (b == 0) { atomicAdd(&g_u1[h1[c]], f1); atomicAdd(&g_u2[h2[c]], f2); }
    }
    if (b == 0) {
        __syncthreads();
        if (tid == 0) g_flag = sflag;
    }
}

// ---------------- k_conv: half2-packed a1, fp32 accumulation (unchanged) ---
#define CONV_SMEM (16384*4 + 768*8)   // 71680 B
__global__ __launch_bounds__(256) void k_conv(const int* __restrict__ h2,
                                              const int* __restrict__ s2)
{
    extern __shared__ float smc[];
    __half2* a1p = (__half2*)smc;             // 16384 entries
    float2*  pt  = (float2*)(smc + 16384);    // 768 entries (shift-as-float, pv)

    int b = blockIdx.x, tid = threadIdx.x;
    const float* ga = g_a1 + b*cD;
    for (int j = tid; j < 16384; j += 256) {
        float v0 = ga[j & (cD - 1)];
        float v1 = ga[(j + 512) & (cD - 1)];
        a1p[j] = __floats2half2_rn(v0, v1);
    }
    for (int c = tid; c < cC; c += 256) {
        float2 e;
        e.x = __int_as_float(cD - h2[c]);
        e.y = g_se1[b*cC + c]*(float)s2[c];
        pt[c] = e;
    }
    __syncthreads();

    int d0 = blockIdx.y*1024 + tid;
    int i1 = d0 + 256;
    float q00 = 0.f, q01 = 0.f, q10 = 0.f, q11 = 0.f;
    #pragma unroll 4
    for (int c = 0; c < cC; ++c) {
        float2 p = pt[c];
        int sh = __float_as_int(p.x);
        float2 va = __half22float2(a1p[d0 + sh]);
        float2 vb = __half22float2(a1p[i1 + sh]);
        q00 += p.y*va.x; q01 += p.y*va.y;
        q10 += p.y*vb.x; q11 += p.y*vb.y;
    }
    float* qo = g_q0 + b*cD;
    qo[d0]       = q00;
    qo[d0 + 512] = q01;
    qo[d0 + 256] = q10;
    qo[d0 + 768] = q11;
}

// ---------------- k_conv_bias: lite (static 12KB smem, global gathers) -----
__global__ __launch_bounds__(256) void k_conv_bias(const int* __restrict__ h1,
                                                   const int* __restrict__ h2,
                                                   const int* __restrict__ s1,
                                                   const int* __restrict__ s2)
{
    __shared__ int   psh2[cC], psh1[cC];
    __shared__ float ps1[cC], ps2[cC];
    if (g_flag == 0) return;
    int b = blockIdx.x, tid = threadIdx.x;
    for (int c = tid; c < cC; c += 256) {
        psh2[c] = cD - h2[c]; psh1[c] = cD - h1[c];
        ps1[c] = (float)s1[c]; ps2[c] = (float)s2[c];
    }
    __syncthreads();
    const float* a1 = g_a1 + b*cD;
    const float* a2 = g_a2 + b*cD;
    int dbase = blockIdx.y*1024 + tid;
    for (int j = 0; j < 4; ++j) {
        int d = dbase + j*256;
        float q1 = 0.f, q2 = 0.f;
        for (int c = 0; c < cC; ++c) {
            int i2 = (d + psh2[c]) & (cD - 1);
            int i1v = (d + psh1[c]) & (cD - 1);
            q1 += ps2[c]*__ldg(a1 + i2) + ps1[c]*__ldg(a2 + i1v);
            q2 += ps2[c]*__ldg(g_u1 + i2);
        }
        g_q1[b*cD + d] = q1;
        if (b == 0) g_q2[d] = q2;
    }
}

// ---------------- k_quad_mma: fp16 m16n8k16, M=160 x N=64 (unchanged) ------
#define SQH_OFF  0
#define SH1_OFF  4096
#define SRED_OFF (SH1_OFF + 768)
#define SA_OFF   (SRED_OFF + 160)
#define SB_OFF   (SA_OFF + 160*36)
#define SMEM_Q   (SB_OFF + 64*36)

__global__ __launch_bounds__(256) void k_quad_mma(const int* __restrict__ h1,
                                                  const int* __restrict__ h2)
{
    extern __shared__ float sm[];
    unsigned short* sQh = (unsigned short*)sm;
    int*      sH1L = (int*)(sm + SH1_OFF);
    float*    sRed = sm + SRED_OFF;
    unsigned* sA   = (unsigned*)(sm + SA_OFF);
    unsigned* sB   = (unsigned*)(sm + SB_OFF);

    int b = blockIdx.x, c2base = blockIdx.y*64;
    int tid = threadIdx.x, lane = tid & 31, warp = tid >> 5;
    int wm = warp & 1, wn = warp >> 1;
    int t4 = lane & 3, qr = lane >> 2;

    const float* qsrc = g_q0 + b*cD;
    for (int j = tid; j < cD; j += 256)
        sQh[j] = __half_as_ushort(__float2half_rn(qsrc[j]));
    for (int i = tid; i < cC; i += 256) {
        int jj = (i >> 1) & 7;
        int p = (jj >> 1) | ((jj & 1) << 2);
        sH1L[i] = h1[(i & ~15) | (p << 1) | (i & 1)];
    }
    if (tid < MPAD) sRed[tid] = 0.f;
    int gn = tid >> 2, gq = tid & 3;
    int h2v = h2[c2base + gn];
    __syncthreads();

    const __half* x1p = g_x1h + (size_t)b*MPAD*cC;

    float acc[5][2][4];
    #pragma unroll
    for (int mi = 0; mi < 5; ++mi)
        #pragma unroll
        for (int ni = 0; ni < 2; ++ni)
            #pragma unroll
            for (int j = 0; j < 4; ++j) acc[mi][ni][j] = 0.f;

    for (int r = 0; r < 12; ++r) {
        #pragma unroll
        for (int i = 0; i < 5; ++i) {
            int e = tid + i*256;
            int row = e >> 3, kq = e & 7;
            uint4 v = *(const uint4*)(x1p + (size_t)row*cC + r*64 + kq*8);
            *(uint4*)(sA + row*36 + kq*4) = v;
        }
        {
            const int* hL = sH1L + r*64;
            #pragma unroll
            for (int j = 0; j < 8; ++j) {
                int jj = gq*8 + j;
                unsigned u0 = sQh[(hL[2*jj]     + h2v) & (cD - 1)];
                unsigned u1 = sQh[(hL[2*jj + 1] + h2v) & (cD - 1)];
                sB[gn*36 + jj] = u0 | (u1 << 16);
            }
        }
        __syncthreads();

        #pragma unroll
        for (int ks = 0; ks < 4; ++ks) {
            uint2 bfr[2];
            #pragma unroll
            for (int ni = 0; ni < 2; ++ni) {
                int n0 = wn*16 + ni*8 + qr;
                bfr[ni] = *(const uint2*)(sB + n0*36 + ks*8 + 2*t4);
            }
            #pragma unroll
            for (int mi = 0; mi < 5; ++mi) {
                int r0 = wm*80 + mi*16 + qr;
                uint2 aA = *(const uint2*)(sA + r0*36 + ks*8 + 2*t4);
                uint2 aB = *(const uint2*)(sA + (r0 + 8)*36 + ks*8 + 2*t4);
                #pragma unroll
                for (int ni = 0; ni < 2; ++ni) {
                    asm volatile(
                        "mma.sync.aligned.m16n8k16.row.col.f32.f16.f16.f32 "
                        "{%0,%1,%2,%3}, {%4,%5,%6,%7}, {%8,%9}, {%0,%1,%2,%3};"
                        : "+f"(acc[mi][ni][0]), "+f"(acc[mi][ni][1]),
                          "+f"(acc[mi][ni][2]), "+f"(acc[mi][ni][3])
                        : "r"(aA.x), "r"(aB.x), "r"(aA.y), "r"(aB.y),
                          "r"(bfr[ni].x), "r"(bfr[ni].y));
                }
            }
        }
        __syncthreads();
    }

    const float* x2p = g_x2 + (size_t)b*MPAD*cC;
    #pragma unroll
    for (int mi = 0; mi < 5; ++mi) {
        int r0 = wm*80 + mi*16 + qr;
        int r1 = r0 + 8;
        float s0 = 0.f, s1v = 0.f;
        #pragma unroll
        for (int ni = 0; ni < 2; ++ni) {
            int col = c2base + wn*16 + ni*8 + 2*t4;
            float2 xa = *(const float2*)(x2p + (size_t)r0*cC + col);
            float2 xb = *(const float2*)(x2p + (size_t)r1*cC + col);
            s0  += acc[mi][ni][0]*xa.x + acc[mi][ni][1]*xa.y;
            s1v += acc[mi][ni][2]*xb.x + acc[mi][ni][3]*xb.y;
        }
        atomicAdd(&sRed[r0], s0);
        atomicAdd(&sRed[r1], s1v);
    }
    __syncthreads();
    if (tid < MPAD) atomicAdd(&g_A[b*MPAD + tid], sRed[tid]);
}

// ---------------- k_quad_bias: lite (static 33KB smem, global q) -----------
__global__ __launch_bounds__(256) void k_quad_bias(const float* __restrict__ img,
                                                   const int* __restrict__ h1,
                                                   const int* __restrict__ h2,
                                                   const float* __restrict__ tok,
                                                   const int* __restrict__ s1,
                                                   const int* __restrict__ s2)
{
    __shared__ float sX1[32*161];
    __shared__ int   sH1[cC];
    __shared__ float sS1[cC], sS2[cC], sTk[cC];

    if (g_flag == 0) return;
    int z = blockIdx.z + 1;
    int b = blockIdx.x, c2base = blockIdx.y*64;
    int tx = threadIdx.x & 15, ty = threadIdx.x >> 4, tid = threadIdx.x;

    const float* qg = (z == 1) ? (g_q1 + b*cD) : g_q2;
    for (int j = tid; j < cC; j += 256) {
        sH1[j] = h1[j];
        sS1[j] = (float)s1[j]; sS2[j] = (float)s2[j];
        sTk[j] = tok[cC + j];
    }
    __syncthreads();

    int h2r[4];
    #pragma unroll
    for (int n = 0; n < 4; ++n) h2r[n] = h2[c2base + tx + 16*n];

    float acc[10][4];
    #pragma unroll
    for (int m = 0; m < 10; ++m)
        #pragma unroll
        for (int n = 0; n < 4; ++n) acc[m][n] = 0.f;

    for (int k0 = 0; k0 < cC; k0 += 32) {
        __syncthreads();
        #pragma unroll
        for (int i = 0; i < 20; ++i) {
            int e = tid + i*256;
            int kt = e & 31, s = e >> 5;
            int c1 = k0 + kt;
            float v = 0.f;
            if (s < cS) v = (img[(b*cS + s)*cC + c1] + sTk[c1])*sS1[c1];
            sX1[kt*161 + s] = v;
        }
        __syncthreads();
        for (int kt = 0; kt < 32; ++kt) {
            int h1v = sH1[k0 + kt];
            float x1r[10];
            #pragma unroll
            for (int m = 0; m < 10; ++m) x1r[m] = sX1[kt*161 + ty + 16*m];
            float qv[4];
            #pragma unroll
            for (int n = 0; n < 4; ++n) qv[n] = __ldg(qg + ((h1v + h2r[n]) & (cD - 1)));
            #pragma unroll
            for (int m = 0; m < 10; ++m)
                #pragma unroll
                for (int n = 0; n < 4; ++n)
                    acc[m][n] += x1r[m]*qv[n];
        }
    }

    #pragma unroll
    for (int m = 0; m < 10; ++m) {
        int s = ty + 16*m;
        if (s >= cS) continue;
        float al = 0.f;
        #pragma unroll
        for (int n = 0; n < 4; ++n) {
            int c2 = c2base + tx + 16*n;
            float x2v = (img[(b*cS + s)*cC + c2] + sTk[c2])*sS2[c2];
            al += acc[m][n]*x2v;
        }
        atomicAdd(&g_A[(z*cB + b)*MPAD + s], al);
    }
}

// ---------------- k_final --------------------------------------------------
__global__ void k_final(const float* __restrict__ W_s2, const float* __restrict__ b_s2,
                        const float* __restrict__ W_out, const float* __restrict__ b_out,
                        float* __restrict__ out)
{
    int tid = threadIdx.x;
    int b = tid >> 5, lane = tid & 31;
    float bpv[5]; float ssum = 0.f;
    #pragma unroll
    for (int i = 0; i < 5; ++i) {
        int s = lane + 32*i;
        float bp = 0.f;
        if (s < cS) {
            float w = W_s2[s], be = b_s2[s];
            float ip = w*w*g_A[b*MPAD + s]
                     + w*be*g_A[(cB + b)*MPAD + s]
                     + be*be*g_A[(2*cB + b)*MPAD + s];
            float sg = (ip > 0.f) ? 1.f : ((ip < 0.f) ? -1.f : 0.f);
            bp = sg*sqrtf(fabsf(ip) + 1e-5f);
        }
        bpv[i] = bp;
        ssum += bp*bp;
    }
    for (int o = 16; o > 0; o >>= 1) ssum += __shfl_xor_sync(0xffffffffu, ssum, o);
    float norm = fmaxf(sqrtf(ssum), 1e-12f);
    float acc = 0.f;
    #pragma unroll
    for (int i = 0; i < 5; ++i) {
        int s = lane + 32*i;
        if (s < cS) acc += bpv[i]*W_out[s];
    }
    for (int o = 16; o > 0; o >>= 1) acc += __shfl_xor_sync(0xffffffffu, acc, o);
    if (lane == 0) out[b] = acc/norm + b_out[0];
}

extern "C" void kernel_launch(void* const* d_in, const int* in_sizes, int n_in,
                              void* d_out, int out_size)
{
    int base = (in_sizes[7] == 1) ? 8 : 7;
    const float* sensor = (const float*)d_in[0];
    const float* img    = (const float*)d_in[1];
    const int*   h1     = (const int*)  d_in[3];
    const int*   h2     = (const int*)  d_in[4];
    const int*   s1     = (const int*)  d_in[5];
    const int*   s2     = (const int*)  d_in[6];
    const float* Wsen   = (const float*)d_in[base+0];
    const float* bsen   = (const float*)d_in[base+1];
    const float* Ws2    = (const float*)d_in[base+2];
    const float* bs2    = (const float*)d_in[base+3];
    const float* Wout   = (const float*)d_in[base+4];
    const float* bout   = (const float*)d_in[base+5];
    const float* tok    = (const float*)d_in[base+6];
    float* out = (float*)d_out;

    static int cfg = 0;
    if (!cfg) {
        cudaFuncSetAttribute(k_conv,     cudaFuncAttributeMaxDynamicSharedMemorySize, CONV_SMEM);
        cudaFuncSetAttribute(k_quad_mma, cudaFuncAttributeMaxDynamicSharedMemorySize, SMEM_Q*4);
        cfg = 1;
    }

    k_prep_se1<<<dim3(cB, cS + 1), 256>>>(img, tok, s1, s2, sensor, Wsen, bsen, h1, h2, bs2);
    k_conv<<<dim3(cB, 8), 256, CONV_SMEM>>>(h2, s2);
    k_conv_bias<<<dim3(cB, 8), 256>>>(h1, h2, s1, s2);
    k_quad_mma<<<dim3(cB, 12), 256, SMEM_Q*4>>>(h1, h2);
    k_quad_bias<<<dim3(cB, 12, 2), 256>>>(img, h1, h2, tok, s1, s2);
    k_final<<<1, 1024>>>(Ws2, bs2, Wout, bout, out);
}

// round 12
// speedup vs baseline: 1.5414x; 1.1190x over previous
#include <cuda_runtime.h>
#include <cuda_fp16.h>
#include <math.h>

#define cB 32
#define cS 145
#define cC 768
#define cD 8192
#define cSN 64
#define MPAD 160

__device__ float g_se1[cB*cC];
__device__ float g_a1[cB*cD];
__device__ float g_a2[cB*cD];
__device__ float g_u1[cD];
__device__ float g_u2[cD];
__device__ float g_q0[cB*cD];
__device__ float g_q1[cB*cD];
__device__ float g_q2[cD];
__device__ float g_A[3*cB*MPAD];
__device__ int   g_flag;
__device__ __half g_x1h[cB*MPAD*cC];  // fp16 X1t, chunk-packed per 64-k block
__device__ float  g_x2[cB*MPAD*cC];   // exact X2t; pad rows stay 0

// ---------------- k_prep_se1: fused prep (y<145) + se1 (y==145) ------------
// X1 chunk layout per 64-k block (4 groups g0..g3 of 16 k):
//   chunk = (g>>1)*4 + (p&3), slot = (g&1)*2 + (p>>2)  [p = (k>>1)&7]
//   pos   = chunk*8 + slot*2 + (k&1)
__global__ void k_prep_se1(const float* __restrict__ img, const float* __restrict__ tok,
                           const int* __restrict__ s1, const int* __restrict__ s2,
                           const float* __restrict__ sensor, const float* __restrict__ Wsen,
                           const float* __restrict__ bsen, const int* __restrict__ h1,
                           const int* __restrict__ h2, const float* __restrict__ b_s2)
{
    int b = blockIdx.x, y = blockIdx.y, tid = threadIdx.x;
    if (y < cS) {
        size_t o = (size_t)(b*MPAD + y)*cC;
        const float* ir = img + ((size_t)b*cS + y)*cC;
        for (int c = tid; c < cC; c += 256) {
            float f1 = (float)s1[c], f2 = (float)s2[c];
            float v = ir[c] + tok[cC + c];
            int g = (c >> 4) & 3, p = (c >> 1) & 7, par = c & 1;
            int chunk = (g >> 1)*4 + (p & 3);
            int sl = (g & 1)*2 + (p >> 2);
            int pos = (c & ~63) | (chunk*8 + sl*2 + par);
            g_x1h[o + pos] = __float2half_rn(v*f1);
            g_x2[o + c]    = v*f2;
        }
        return;
    }
    __shared__ float ss[cSN];
    __shared__ int sflag;
    for (int j = tid; j < cD; j += 256) { g_a1[b*cD + j] = 0.f; g_a2[b*cD + j] = 0.f; }
    if (b == 0) for (int j = tid; j < cD; j += 256) { g_u1[j] = 0.f; g_u2[j] = 0.f; }
    #pragma unroll
    for (int z = 0; z < 3; ++z)
        for (int j = tid; j < MPAD; j += 256) g_A[(z*cB + b)*MPAD + j] = 0.f;

    if (tid == 0) sflag = 0;
    if (tid < cSN) ss[tid] = sensor[b*cSN + tid];
    __syncthreads();
    if (b == 0 && tid < cS && b_s2[tid] != 0.f) atomicOr(&sflag, 1);

    for (int c = tid; c < cC; c += 256) {
        float acc = bsen[c];
        const float* w = Wsen + c*cSN;
        #pragma unroll 16
        for (int n = 0; n < cSN; ++n) acc += ss[n]*w[n];
        g_se1[b*cC + c] = acc;
        float f1 = (float)s1[c], f2 = (float)s2[c];
        atomicAdd(&g_a1[b*cD + h1[c]], acc*f1);
        atomicAdd(&g_a2[b*cD + h2[c]], acc*f2);
        if (b == 0) { atomicAdd(&g_u1[h1[c]], f1); atomicAdd(&g_u2[h2[c]], f2); }
    }
    if (b == 0) {
        __syncthreads();
        if (tid == 0) g_flag = sflag;
    }
}

// ---------------- k_conv: half2-packed a1, fp32 accumulation (unchanged) ---
#define CONV_SMEM (16384*4 + 768*8)   // 71680 B
__global__ __launch_bounds__(256) void k_conv(const int* __restrict__ h2,
                                              const int* __restrict__ s2)
{
    extern __shared__ float smc[];
    __half2* a1p = (__half2*)smc;
    float2*  pt  = (float2*)(smc + 16384);

    int b = blockIdx.x, tid = threadIdx.x;
    const float* ga = g_a1 + b*cD;
    for (int j = tid; j < 16384; j += 256) {
        float v0 = ga[j & (cD - 1)];
        float v1 = ga[(j + 512) & (cD - 1)];
        a1p[j] = __floats2half2_rn(v0, v1);
    }
    for (int c = tid; c < cC; c += 256) {
        float2 e;
        e.x = __int_as_float(cD - h2[c]);
        e.y = g_se1[b*cC + c]*(float)s2[c];
        pt[c] = e;
    }
    __syncthreads();

    int d0 = blockIdx.y*1024 + tid;
    int i1 = d0 + 256;
    float q00 = 0.f, q01 = 0.f, q10 = 0.f, q11 = 0.f;
    #pragma unroll 4
    for (int c = 0; c < cC; ++c) {
        float2 p = pt[c];
        int sh = __float_as_int(p.x);
        float2 va = __half22float2(a1p[d0 + sh]);
        float2 vb = __half22float2(a1p[i1 + sh]);
        q00 += p.y*va.x; q01 += p.y*va.y;
        q10 += p.y*vb.x; q11 += p.y*vb.y;
    }
    float* qo = g_q0 + b*cD;
    qo[d0]       = q00;
    qo[d0 + 512] = q01;
    qo[d0 + 256] = q10;
    qo[d0 + 768] = q11;
}

// ---------------- k_conv_bias: lite (unchanged) ----------------------------
__global__ __launch_bounds__(256) void k_conv_bias(const int* __restrict__ h1,
                                                   const int* __restrict__ h2,
                                                   const int* __restrict__ s1,
                                                   const int* __restrict__ s2)
{
    __shared__ int   psh2[cC], psh1[cC];
    __shared__ float ps1[cC], ps2[cC];
    if (g_flag == 0) return;
    int b = blockIdx.x, tid = threadIdx.x;
    for (int c = tid; c < cC; c += 256) {
        psh2[c] = cD - h2[c]; psh1[c] = cD - h1[c];
        ps1[c] = (float)s1[c]; ps2[c] = (float)s2[c];
    }
    __syncthreads();
    const float* a1 = g_a1 + b*cD;
    const float* a2 = g_a2 + b*cD;
    int dbase = blockIdx.y*1024 + tid;
    for (int j = 0; j < 4; ++j) {
        int d = dbase + j*256;
        float q1 = 0.f, q2 = 0.f;
        for (int c = 0; c < cC; ++c) {
            int i2 = (d + psh2[c]) & (cD - 1);
            int i1v = (d + psh1[c]) & (cD - 1);
            q1 += ps2[c]*__ldg(a1 + i2) + ps1[c]*__ldg(a2 + i1v);
            q2 += ps2[c]*__ldg(g_u1 + i2);
        }
        g_q1[b*cD + d] = q1;
        if (b == 0) g_q2[d] = q2;
    }
}

// ---------------- k_quad_mma: 4 warps, LDS.128 frags, XOR swizzle ----------
#define SQH_OFF  0                       // 4096 floats (8192 halves)
#define SH1_OFF  4096                    // 768 ints
#define SRED_OFF (SH1_OFF + 768)         // 160
#define SA_OFF   (SRED_OFF + 160)        // 1280 uint4 = 5120 floats
#define SB_OFF   (SA_OFF + 5120)         // 512 uint4 = 2048 floats
#define SMEM_Q   (SB_OFF + 2048)         // 12192 floats = 48768 B

#define MMA16(acc, a0, a1, a2, a3, b0, b1) \
    asm volatile( \
        "mma.sync.aligned.m16n8k16.row.col.f32.f16.f16.f32 " \
        "{%0,%1,%2,%3}, {%4,%5,%6,%7}, {%8,%9}, {%0,%1,%2,%3};" \
        : "+f"((acc)[0]), "+f"((acc)[1]), "+f"((acc)[2]), "+f"((acc)[3]) \
        : "r"(a0), "r"(a1), "r"(a2), "r"(a3), "r"(b0), "r"(b1))

__global__ __launch_bounds__(128) void k_quad_mma(const int* __restrict__ h1,
                                                  const int* __restrict__ h2)
{
    extern __shared__ float sm[];
    unsigned short* sQh = (unsigned short*)sm;
    int*   sH1L = (int*)(sm + SH1_OFF);
    float* sRed = sm + SRED_OFF;
    uint4* sAv  = (uint4*)(sm + SA_OFF);
    uint4* sBv  = (uint4*)(sm + SB_OFF);

    int b = blockIdx.x, c2base = blockIdx.y*64;
    int tid = threadIdx.x, lane = tid & 31, warp = tid >> 5;
    int wm = warp & 1, wn = warp >> 1;
    int t4 = lane & 3, qr = lane >> 2;

    const float* qsrc = g_q0 + b*cD;
    for (int j = tid; j < cD; j += 128)
        sQh[j] = __half_as_ushort(__float2half_rn(qsrc[j]));
    for (int i = tid; i < cC; i += 128) {
        int pos = i & 63, blk = i & ~63;
        int c = pos >> 3, sl = (pos >> 1) & 3, par = pos & 1;
        int g = (c >> 2)*2 + (sl >> 1);
        int p = (c & 3) | ((sl & 1) << 2);
        sH1L[i] = h1[blk | (g*16 + p*2 + par)];
    }
    for (int j = tid; j < MPAD; j += 128) sRed[j] = 0.f;
    int gcol = tid >> 1, gP = tid & 1;
    int h2v = h2[c2base + gcol];
    __syncthreads();

    const __half* x1p = g_x1h + (size_t)b*MPAD*cC;

    float acc[5][4][4];
    #pragma unroll
    for (int mi = 0; mi < 5; ++mi)
        #pragma unroll
        for (int ni = 0; ni < 4; ++ni)
            #pragma unroll
            for (int j = 0; j < 4; ++j) acc[mi][ni][j] = 0.f;

    for (int r = 0; r < 12; ++r) {
        // stage A: 160 rows x 8 chunks, swizzled
        #pragma unroll
        for (int i = 0; i < 10; ++i) {
            int e = tid + i*128;
            int row = e >> 3, ch = e & 7;
            uint4 v = *(const uint4*)(x1p + (size_t)row*cC + r*64 + ch*8);
            sAv[row*8 + (ch ^ (row & 7))] = v;
        }
        // gather B: thread = (col, P-half); 4 chunks x 8 lookups
        {
            const int* hL = sH1L + r*64;
            int cb8 = gcol*8, cm = gcol & 7;
            #pragma unroll
            for (int cc = 0; cc < 4; ++cc) {
                int c = gP*4 + cc;
                unsigned u[4];
                #pragma unroll
                for (int sl = 0; sl < 4; ++sl) {
                    int pos = c*8 + sl*2;
                    unsigned lo = sQh[(hL[pos]     + h2v) & (cD - 1)];
                    unsigned hi = sQh[(hL[pos + 1] + h2v) & (cD - 1)];
                    u[sl] = lo | (hi << 16);
                }
                sBv[cb8 + (c ^ cm)] = make_uint4(u[0], u[1], u[2], u[3]);
            }
        }
        __syncthreads();

        #pragma unroll
        for (int P = 0; P < 2; ++P) {
            uint4 Bv[4];
            #pragma unroll
            for (int ni = 0; ni < 4; ++ni) {
                int n0 = wn*32 + ni*8 + qr;
                Bv[ni] = sBv[n0*8 + ((P*4 + t4) ^ qr)];
            }
            #pragma unroll
            for (int mi = 0; mi < 5; ++mi) {
                int r0 = wm*80 + mi*16 + qr;
                uint4 La = sAv[r0*8 + ((P*4 + t4) ^ qr)];
                uint4 Lb = sAv[(r0 + 8)*8 + ((P*4 + t4) ^ qr)];
                #pragma unroll
                for (int ni = 0; ni < 4; ++ni) {
                    MMA16(acc[mi][ni], La.x, Lb.x, La.y, Lb.y, Bv[ni].x, Bv[ni].y);
                    MMA16(acc[mi][ni], La.z, Lb.z, La.w, Lb.w, Bv[ni].z, Bv[ni].w);
                }
            }
        }
        __syncthreads();
    }

    // epilogue: fold with exact fp32 X2
    const float* x2p = g_x2 + (size_t)b*MPAD*cC;
    #pragma unroll
    for (int mi = 0; mi < 5; ++mi) {
        int r0 = wm*80 + mi*16 + qr;
        int r1 = r0 + 8;
        float s0 = 0.f, s1v = 0.f;
        #pragma unroll
        for (int ni = 0; ni < 4; ++ni) {
            int col = c2base + wn*32 + ni*8 + 2*t4;
            float2 xa = *(const float2*)(x2p + (size_t)r0*cC + col);
            float2 xb = *(const float2*)(x2p + (size_t)r1*cC + col);
            s0  += acc[mi][ni][0]*xa.x + acc[mi][ni][1]*xa.y;
            s1v += acc[mi][ni][2]*xb.x + acc[mi][ni][3]*xb.y;
        }
        atomicAdd(&sRed[r0], s0);
        atomicAdd(&sRed[r1], s1v);
    }
    __syncthreads();
    for (int j = tid; j < MPAD; j += 128) atomicAdd(&g_A[b*MPAD + j], sRed[j]);
}

// ---------------- k_quad_bias: lite (unchanged) ----------------------------
__global__ __launch_bounds__(256) void k_quad_bias(const float* __restrict__ img,
                                                   const int* __restrict__ h1,
                                                   const int* __restrict__ h2,
                                                   const float* __restrict__ tok,
                                                   const int* __restrict__ s1,
                                                   const int* __restrict__ s2)
{
    __shared__ float sX1[32*161];
    __shared__ int   sH1[cC];
    __shared__ float sS1[cC], sS2[cC], sTk[cC];

    if (g_flag == 0) return;
    int z = blockIdx.z + 1;
    int b = blockIdx.x, c2base = blockIdx.y*64;
    int tx = threadIdx.x & 15, ty = threadIdx.x >> 4, tid = threadIdx.x;

    const float* qg = (z == 1) ? (g_q1 + b*cD) : g_q2;
    for (int j = tid; j < cC; j += 256) {
        sH1[j] = h1[j];
        sS1[j] = (float)s1[j]; sS2[j] = (float)s2[j];
        sTk[j] = tok[cC + j];
    }
    __syncthreads();

    int h2r[4];
    #pragma unroll
    for (int n = 0; n < 4; ++n) h2r[n] = h2[c2base + tx + 16*n];

    float acc[10][4];
    #pragma unroll
    for (int m = 0; m < 10; ++m)
        #pragma unroll
        for (int n = 0; n < 4; ++n) acc[m][n] = 0.f;

    for (int k0 = 0; k0 < cC; k0 += 32) {
        __syncthreads();
        #pragma unroll
        for (int i = 0; i < 20; ++i) {
            int e = tid + i*256;
            int kt = e & 31, s = e >> 5;
            int c1 = k0 + kt;
            float v = 0.f;
            if (s < cS) v = (img[(b*cS + s)*cC + c1] + sTk[c1])*sS1[c1];
            sX1[kt*161 + s] = v;
        }
        __syncthreads();
        for (int kt = 0; kt < 32; ++kt) {
            int h1v = sH1[k0 + kt];
            float x1r[10];
            #pragma unroll
            for (int m = 0; m < 10; ++m) x1r[m] = sX1[kt*161 + ty + 16*m];
            float qv[4];
            #pragma unroll
            for (int n = 0; n < 4; ++n) qv[n] = __ldg(qg + ((h1v + h2r[n]) & (cD - 1)));
            #pragma unroll
            for (int m = 0; m < 10; ++m)
                #pragma unroll
                for (int n = 0; n < 4; ++n)
                    acc[m][n] += x1r[m]*qv[n];
        }
    }

    #pragma unroll
    for (int m = 0; m < 10; ++m) {
        int s = ty + 16*m;
        if (s >= cS) continue;
        float al = 0.f;
        #pragma unroll
        for (int n = 0; n < 4; ++n) {
            int c2 = c2base + tx + 16*n;
            float x2v = (img[(b*cS + s)*cC + c2] + sTk[c2])*sS2[c2];
            al += acc[m][n]*x2v;
        }
        atomicAdd(&g_A[(z*cB + b)*MPAD + s], al);
    }
}

// ---------------- k_final --------------------------------------------------
__global__ void k_final(const float* __restrict__ W_s2, const float* __restrict__ b_s2,
                        const float* __restrict__ W_out, const float* __restrict__ b_out,
                        float* __restrict__ out)
{
    int tid = threadIdx.x;
    int b = tid >> 5, lane = tid & 31;
    float bpv[5]; float ssum = 0.f;
    #pragma unroll
    for (int i = 0; i < 5; ++i) {
        int s = lane + 32*i;
        float bp = 0.f;
        if (s < cS) {
            float w = W_s2[s], be = b_s2[s];
            float ip = w*w*g_A[b*MPAD + s]
                     + w*be*g_A[(cB + b)*MPAD + s]
                     + be*be*g_A[(2*cB + b)*MPAD + s];
            float sg = (ip > 0.f) ? 1.f : ((ip < 0.f) ? -1.f : 0.f);
            bp = sg*sqrtf(fabsf(ip) + 1e-5f);
        }
        bpv[i] = bp;
        ssum += bp*bp;
    }
    for (int o = 16; o > 0; o >>= 1) ssum += __shfl_xor_sync(0xffffffffu, ssum, o);
    float norm = fmaxf(sqrtf(ssum), 1e-12f);
    float acc = 0.f;
    #pragma unroll
    for (int i = 0; i < 5; ++i) {
        int s = lane + 32*i;
        if (s < cS) acc += bpv[i]*W_out[s];
    }
    for (int o = 16; o > 0; o >>= 1) acc += __shfl_xor_sync(0xffffffffu, acc, o);
    if (lane == 0) out[b] = acc/norm + b_out[0];
}

extern "C" void kernel_launch(void* const* d_in, const int* in_sizes, int n_in,
                              void* d_out, int out_size)
{
    int base = (in_sizes[7] == 1) ? 8 : 7;
    const float* sensor = (const float*)d_in[0];
    const float* img    = (const float*)d_in[1];
    const int*   h1     = (const int*)  d_in[3];
    const int*   h2     = (const int*)  d_in[4];
    const int*   s1     = (const int*)  d_in[5];
    const int*   s2     = (const int*)  d_in[6];
    const float* Wsen   = (const float*)d_in[base+0];
    const float* bsen   = (const float*)d_in[base+1];
    const float* Ws2    = (const float*)d_in[base+2];
    const float* bs2    = (const float*)d_in[base+3];
    const float* Wout   = (const float*)d_in[base+4];
    const float* bout   = (const float*)d_in[base+5];
    const float* tok    = (const float*)d_in[base+6];
    float* out = (float*)d_out;

    static int cfg = 0;
    if (!cfg) {
        cudaFuncSetAttribute(k_conv,     cudaFuncAttributeMaxDynamicSharedMemorySize, CONV_SMEM);
        cudaFuncSetAttribute(k_quad_mma, cudaFuncAttributeMaxDynamicSharedMemorySize, SMEM_Q*4);
        cfg = 1;
    }

    k_prep_se1<<<dim3(cB, cS + 1), 256>>>(img, tok, s1, s2, sensor, Wsen, bsen, h1, h2, bs2);
    k_conv<<<dim3(cB, 8), 256, CONV_SMEM>>>(h2, s2);
    k_conv_bias<<<dim3(cB, 8), 256>>>(h1, h2, s1, s2);
    k_quad_mma<<<dim3(cB, 12), 128, SMEM_Q*4>>>(h1, h2);
    k_quad_bias<<<dim3(cB, 12, 2), 256>>>(img, h1, h2, tok, s1, s2);
    k_final<<<1, 1024>>>(Ws2, bs2, Wout, bout, out);
}